// round 4
// baseline (speedup 1.0000x reference)
#include <cuda_runtime.h>
#include <cuda_fp16.h>
#include <cstdint>
#include <cstddef>

// ============================ problem constants ============================
#define MDIM   16384
#define NDIM   2048
#define KDIM   2048
#define BM     128
#define BN     128
#define BK     64                    // 64 halfs = 128 B per row
#define KITERS 32                    // KDIM / BK
#define STAGES 3

#define TILES_M (MDIM / BM)          // 128
#define TILES_N (NDIM / BN)          // 16
#define NTILES  (TILES_M * TILES_N)  // 2048
#define GRID    296                  // 2 CTAs per SM, persistent

#define A_BYTES     16384            // 128 rows x 128 B
#define STAGE_BYTES 32768            // A + B
#define SMEM_BYTES  (STAGES * STAGE_BYTES)      // 98304 -> 2 CTAs/SM

// ============================ scratch (no allocs allowed) ============================
__device__ __half g_xq[(size_t)MDIM * KDIM];    // 64 MB quantized activations
__device__ __half g_wq[(size_t)NDIM * KDIM];    // 8 MB  quantized+rram weights

// ============================ helpers ============================
__device__ __forceinline__ uint32_t smem_u32(const void* p) {
    uint32_t a;
    asm("{ .reg .u64 t; cvta.to.shared.u64 t, %1; cvt.u32.u64 %0, t; }"
        : "=r"(a) : "l"(p));
    return a;
}
__device__ __forceinline__ void cp16(uint32_t dst, const void* src) {
    asm volatile("cp.async.cg.shared.global [%0], [%1], 16;"
                 :: "r"(dst), "l"(src) : "memory");
}
__device__ __forceinline__ void ldm_x4(uint32_t* r, uint32_t addr) {
    asm volatile("ldmatrix.sync.aligned.m8n8.x4.shared.b16 {%0,%1,%2,%3}, [%4];"
                 : "=r"(r[0]), "=r"(r[1]), "=r"(r[2]), "=r"(r[3]) : "r"(addr));
}
__device__ __forceinline__ void hmma(float* c, const uint32_t* a,
                                     uint32_t b0, uint32_t b1) {
    asm volatile(
        "mma.sync.aligned.m16n8k16.row.col.f32.f16.f16.f32 "
        "{%0,%1,%2,%3}, {%4,%5,%6,%7}, {%8,%9}, {%0,%1,%2,%3};"
        : "+f"(c[0]), "+f"(c[1]), "+f"(c[2]), "+f"(c[3])
        : "r"(a[0]), "r"(a[1]), "r"(a[2]), "r"(a[3]), "r"(b0), "r"(b1));
}

// ============================ quantize kernels ============================
__device__ __forceinline__ float ternx(float v) {
    return v > 0.33f ? 0.5f : (v < -0.33f ? -0.5f : 0.0f);
}
__device__ __forceinline__ float ternw(float v) {
    return v > 0.2f ? 0.6f : (v < -0.2f ? -0.6f : 0.0f);
}

__global__ void __launch_bounds__(256) qx_kernel(const float* __restrict__ x) {
    size_t i = (size_t)blockIdx.x * 256 + threadIdx.x;   // 8 elems / thread
    const float4* p = reinterpret_cast<const float4*>(x) + i * 2;
    float4 a = p[0], b = p[1];
    __half2 h0 = __floats2half2_rn(ternx(a.x), ternx(a.y));
    __half2 h1 = __floats2half2_rn(ternx(a.z), ternx(a.w));
    __half2 h2 = __floats2half2_rn(ternx(b.x), ternx(b.y));
    __half2 h3 = __floats2half2_rn(ternx(b.z), ternx(b.w));
    uint4 v;
    v.x = *reinterpret_cast<uint32_t*>(&h0);
    v.y = *reinterpret_cast<uint32_t*>(&h1);
    v.z = *reinterpret_cast<uint32_t*>(&h2);
    v.w = *reinterpret_cast<uint32_t*>(&h3);
    reinterpret_cast<uint4*>(g_xq)[i] = v;
}

__global__ void __launch_bounds__(256) qw_kernel(const float* __restrict__ w,
                                                 const float* __restrict__ rv) {
    size_t i = (size_t)blockIdx.x * 256 + threadIdx.x;
    const float4* pw = reinterpret_cast<const float4*>(w) + i * 2;
    const float4* pr = reinterpret_cast<const float4*>(rv) + i * 2;
    float4 wa = pw[0], wb = pw[1];
    float4 ra = pr[0], rb = pr[1];
    __half2 h0 = __floats2half2_rn(ternw(wa.x) + ra.x, ternw(wa.y) + ra.y);
    __half2 h1 = __floats2half2_rn(ternw(wa.z) + ra.z, ternw(wa.w) + ra.w);
    __half2 h2 = __floats2half2_rn(ternw(wb.x) + rb.x, ternw(wb.y) + rb.y);
    __half2 h3 = __floats2half2_rn(ternw(wb.z) + rb.z, ternw(wb.w) + rb.w);
    uint4 v;
    v.x = *reinterpret_cast<uint32_t*>(&h0);
    v.y = *reinterpret_cast<uint32_t*>(&h1);
    v.z = *reinterpret_cast<uint32_t*>(&h2);
    v.w = *reinterpret_cast<uint32_t*>(&h3);
    reinterpret_cast<uint4*>(g_wq)[i] = v;
}

// ============================ GEMM kernel (persistent, 2 CTA/SM) ============================
__global__ void __launch_bounds__(256, 2)
gemm_kernel(float* __restrict__ out) {
    extern __shared__ __align__(1024) char smem[];
    const uint32_t sb = smem_u32(smem);
    const int tid  = threadIdx.x;
    const int lane = tid & 31;
    const int wid  = tid >> 5;
    const int wm   = wid >> 2;       // 0..1 : 64-row half
    const int wn   = wid & 3;        // 0..3 : 32-col strip
    const int bid  = blockIdx.x;

    // per-thread cp.async geometry: rA = base row (0..31), 4 rows at +32 each
    const int rA         = tid >> 3;                          // 0..31
    const int ch         = tid & 7;                           // 16B chunk in row
    const uint32_t col_sw = ((uint32_t)ch * 16) ^ (((uint32_t)rA & 7) << 4);

    // ldmatrix addressing (SW128)
    const uint32_t kxor     = (uint32_t)(lane & 7) << 4;
    const uint32_t rowA_off = (uint32_t)(wm * 64 + (lane & 15)) * 128;
    const uint32_t rowB_off = A_BYTES + (uint32_t)(wn * 32 + (lane & 15)) * 128;
    const uint32_t khi      = (uint32_t)(lane & 16);          // +16B upper k-half

    // number of tiles this CTA owns; tile j -> id = bid + j*GRID
    const int L = (NTILES - bid + GRID - 1) / GRID;
    const int V = L * KITERS;                                 // virtual iterations

    auto produce = [&](int v) {
        const int t  = bid + (v >> 5) * GRID;                 // tile id
        const int k  = v & 31;
        const int m0 = (t >> 4) * BM;                         // n-fastest order
        const int n0 = (t & 15) * BN;
        const uint32_t st = sb + (uint32_t)(((uint32_t)v) % STAGES) * STAGE_BYTES;
        const __half* pa = g_xq + (size_t)(m0 + rA) * KDIM + ch * 8 + (size_t)k * BK;
        const __half* pb = g_wq + (size_t)(n0 + rA) * KDIM + ch * 8 + (size_t)k * BK;
        #pragma unroll
        for (int n = 0; n < 4; n++)
            cp16(st + (uint32_t)(rA + n * 32) * 128 + col_sw,
                 pa + (size_t)n * 32 * KDIM);
        #pragma unroll
        for (int n = 0; n < 4; n++)
            cp16(st + A_BYTES + (uint32_t)(rA + n * 32) * 128 + col_sw,
                 pb + (size_t)n * 32 * KDIM);
        asm volatile("cp.async.commit_group;" ::: "memory");
    };

    float acc[4][2][2][4];                                    // [mf][p][h][4]
    #pragma unroll
    for (int mf = 0; mf < 4; mf++)
        #pragma unroll
        for (int p = 0; p < 2; p++)
            #pragma unroll
            for (int h = 0; h < 2; h++)
                acc[mf][p][h][0] = acc[mf][p][h][1] =
                acc[mf][p][h][2] = acc[mf][p][h][3] = 0.f;

    produce(0);
    produce(1);

    for (int v = 0; v < V; v++) {
        asm volatile("cp.async.wait_group 1;" ::: "memory");
        __syncthreads();
        if (v + 2 < V) produce(v + 2);
        else asm volatile("cp.async.commit_group;" ::: "memory");

        const uint32_t st = sb + (uint32_t)(((uint32_t)v) % STAGES) * STAGE_BYTES;
        #pragma unroll
        for (int ks = 0; ks < 4; ks++) {
            const uint32_t colk = ((uint32_t)(ks * 32) + khi) ^ kxor;
            uint32_t a[4][4];
            #pragma unroll
            for (int mf = 0; mf < 4; mf++)
                ldm_x4(a[mf], st + rowA_off + (uint32_t)mf * 2048 + colk);
            uint32_t b[2][4];
            #pragma unroll
            for (int p = 0; p < 2; p++)
                ldm_x4(b[p], st + rowB_off + (uint32_t)p * 2048 + colk);
            #pragma unroll
            for (int mf = 0; mf < 4; mf++) {
                #pragma unroll
                for (int p = 0; p < 2; p++) {
                    hmma(acc[mf][p][0], a[mf], b[p][0], b[p][2]);
                    hmma(acc[mf][p][1], a[mf], b[p][1], b[p][3]);
                }
            }
        }

        if ((v & 31) == 31) {
            // epilogue for finished tile
            const int t  = bid + (v >> 5) * GRID;
            const int m0 = (t >> 4) * BM;
            const int n0 = (t & 15) * BN;
            const int rbase = m0 + wm * 64 + (lane >> 2);
            const int cbase = n0 + wn * 32 + (lane & 3) * 2;
            #pragma unroll
            for (int mf = 0; mf < 4; mf++) {
                #pragma unroll
                for (int p = 0; p < 2; p++) {
                    #pragma unroll
                    for (int h = 0; h < 2; h++) {
                        const int col = cbase + p * 16 + h * 8;
                        float* o0 = out + (size_t)(rbase + mf * 16) * NDIM + col;
                        float* o1 = out + (size_t)(rbase + mf * 16 + 8) * NDIM + col;
                        *reinterpret_cast<float2*>(o0) =
                            make_float2(acc[mf][p][h][0], acc[mf][p][h][1]);
                        *reinterpret_cast<float2*>(o1) =
                            make_float2(acc[mf][p][h][2], acc[mf][p][h][3]);
                        acc[mf][p][h][0] = acc[mf][p][h][1] = 0.f;
                        acc[mf][p][h][2] = acc[mf][p][h][3] = 0.f;
                    }
                }
            }
        }
    }
}

// ============================ host launcher ============================
extern "C" void kernel_launch(void* const* d_in, const int* in_sizes, int n_in,
                              void* d_out, int out_size) {
    (void)in_sizes; (void)n_in; (void)out_size;
    const float* x  = (const float*)d_in[0];
    const float* w  = (const float*)d_in[1];
    const float* rv = (const float*)d_in[2];
    float* out = (float*)d_out;

    qx_kernel<<<16384, 256>>>(x);        // 16384*256*8 = 16384*2048
    qw_kernel<<<2048, 256>>>(w, rv);     // 2048*256*8  = 2048*2048

    static bool configured = false;
    if (!configured) {
        cudaFuncSetAttribute((const void*)gemm_kernel,
                             cudaFuncAttributeMaxDynamicSharedMemorySize, SMEM_BYTES);
        configured = true;
    }
    gemm_kernel<<<GRID, 256, SMEM_BYTES>>>(out);
}

// round 5
// speedup vs baseline: 1.0172x; 1.0172x over previous
#include <cuda_runtime.h>
#include <cuda_fp16.h>
#include <cstdint>
#include <cstddef>

// ============================ problem constants ============================
#define MDIM   16384
#define NDIM   2048
#define KDIM   2048
#define BM     128
#define BN     256
#define BK     64                    // 64 halfs = 128 B per row
#define KITERS 32                    // KDIM / BK
#define STAGES 3

#define TILES_M (MDIM / BM)          // 128
#define TILES_N (NDIM / BN)          // 8
#define NTILES  (TILES_M * TILES_N)  // 1024
#define GRID    148                  // persistent, 1 CTA/SM

#define A_BYTES     16384            // 128 rows x 128 B
#define B_BYTES     32768            // 256 rows x 128 B
#define STAGE_BYTES (A_BYTES + B_BYTES)        // 48 KB
#define SMEM_BYTES  (STAGES * STAGE_BYTES)     // 147456

// ============================ scratch (no allocs allowed) ============================
__device__ __half g_xq[(size_t)MDIM * KDIM];    // 64 MB quantized activations
__device__ __half g_wq[(size_t)NDIM * KDIM];    // 8 MB  quantized+rram weights

// ============================ helpers ============================
__device__ __forceinline__ uint32_t smem_u32(const void* p) {
    uint32_t a;
    asm("{ .reg .u64 t; cvta.to.shared.u64 t, %1; cvt.u32.u64 %0, t; }"
        : "=r"(a) : "l"(p));
    return a;
}
__device__ __forceinline__ void cp16(uint32_t dst, const void* src) {
    asm volatile("cp.async.cg.shared.global [%0], [%1], 16;"
                 :: "r"(dst), "l"(src) : "memory");
}
__device__ __forceinline__ void ldm_x4(uint32_t* r, uint32_t addr) {
    asm volatile("ldmatrix.sync.aligned.m8n8.x4.shared.b16 {%0,%1,%2,%3}, [%4];"
                 : "=r"(r[0]), "=r"(r[1]), "=r"(r[2]), "=r"(r[3]) : "r"(addr));
}
__device__ __forceinline__ void hmma(float* c, const uint32_t* a,
                                     uint32_t b0, uint32_t b1) {
    asm volatile(
        "mma.sync.aligned.m16n8k16.row.col.f32.f16.f16.f32 "
        "{%0,%1,%2,%3}, {%4,%5,%6,%7}, {%8,%9}, {%0,%1,%2,%3};"
        : "+f"(c[0]), "+f"(c[1]), "+f"(c[2]), "+f"(c[3])
        : "r"(a[0]), "r"(a[1]), "r"(a[2]), "r"(a[3]), "r"(b0), "r"(b1));
}

// ============================ quantize kernels ============================
__device__ __forceinline__ float ternx(float v) {
    return v > 0.33f ? 0.5f : (v < -0.33f ? -0.5f : 0.0f);
}
__device__ __forceinline__ float ternw(float v) {
    return v > 0.2f ? 0.6f : (v < -0.2f ? -0.6f : 0.0f);
}

__global__ void __launch_bounds__(256) qx_kernel(const float* __restrict__ x) {
    size_t i = (size_t)blockIdx.x * 256 + threadIdx.x;   // 8 elems / thread
    const float4* p = reinterpret_cast<const float4*>(x) + i * 2;
    float4 a = p[0], b = p[1];
    __half2 h0 = __floats2half2_rn(ternx(a.x), ternx(a.y));
    __half2 h1 = __floats2half2_rn(ternx(a.z), ternx(a.w));
    __half2 h2 = __floats2half2_rn(ternx(b.x), ternx(b.y));
    __half2 h3 = __floats2half2_rn(ternx(b.z), ternx(b.w));
    uint4 v;
    v.x = *reinterpret_cast<uint32_t*>(&h0);
    v.y = *reinterpret_cast<uint32_t*>(&h1);
    v.z = *reinterpret_cast<uint32_t*>(&h2);
    v.w = *reinterpret_cast<uint32_t*>(&h3);
    reinterpret_cast<uint4*>(g_xq)[i] = v;
}

__global__ void __launch_bounds__(256) qw_kernel(const float* __restrict__ w,
                                                 const float* __restrict__ rv) {
    size_t i = (size_t)blockIdx.x * 256 + threadIdx.x;
    const float4* pw = reinterpret_cast<const float4*>(w) + i * 2;
    const float4* pr = reinterpret_cast<const float4*>(rv) + i * 2;
    float4 wa = pw[0], wb = pw[1];
    float4 ra = pr[0], rb = pr[1];
    __half2 h0 = __floats2half2_rn(ternw(wa.x) + ra.x, ternw(wa.y) + ra.y);
    __half2 h1 = __floats2half2_rn(ternw(wa.z) + ra.z, ternw(wa.w) + ra.w);
    __half2 h2 = __floats2half2_rn(ternw(wb.x) + rb.x, ternw(wb.y) + rb.y);
    __half2 h3 = __floats2half2_rn(ternw(wb.z) + rb.z, ternw(wb.w) + rb.w);
    uint4 v;
    v.x = *reinterpret_cast<uint32_t*>(&h0);
    v.y = *reinterpret_cast<uint32_t*>(&h1);
    v.z = *reinterpret_cast<uint32_t*>(&h2);
    v.w = *reinterpret_cast<uint32_t*>(&h3);
    reinterpret_cast<uint4*>(g_wq)[i] = v;
}

// ============================ GEMM kernel (persistent, warp tile 64x64) ============================
__global__ void __launch_bounds__(256, 1)
gemm_kernel(float* __restrict__ out) {
    extern __shared__ __align__(1024) char smem[];
    const uint32_t sb = smem_u32(smem);
    const int tid  = threadIdx.x;
    const int lane = tid & 31;
    const int wid  = tid >> 5;
    const int wm   = wid >> 2;       // 0..1 : 64-row half (M)
    const int wn   = wid & 3;        // 0..3 : 64-col strip (N)
    const int bid  = blockIdx.x;

    // per-thread cp.async geometry (12 x 16B chunks per stage)
    const int rA          = tid >> 3;                         // 0..31
    const int ch          = tid & 7;                          // 16B chunk in 128B row
    const uint32_t col_sw = ((uint32_t)ch * 16) ^ (((uint32_t)rA & 7) << 4);

    // ldmatrix addressing (SW128)
    const uint32_t kxor     = (uint32_t)(lane & 7) << 4;
    const uint32_t rowA_off = (uint32_t)(wm * 64 + (lane & 15)) * 128;
    const uint32_t rowB_off = A_BYTES + (uint32_t)(wn * 64 + (lane & 15)) * 128;
    const uint32_t khi      = (uint32_t)(lane & 16);          // +16B upper k-half

    const int L = (NTILES - bid + GRID - 1) / GRID;           // tiles owned
    const int V = L * KITERS;

    auto produce = [&](int v) {
        const int t  = bid + (v >> 5) * GRID;
        const int k  = v & 31;
        const int m0 = (t >> 3) * BM;                         // n-fastest order
        const int n0 = (t & 7) * BN;
        const uint32_t st = sb + (uint32_t)(((uint32_t)v) % STAGES) * STAGE_BYTES;
        const __half* pa = g_xq + (size_t)(m0 + rA) * KDIM + ch * 8 + (size_t)k * BK;
        const __half* pb = g_wq + (size_t)(n0 + rA) * KDIM + ch * 8 + (size_t)k * BK;
        #pragma unroll
        for (int n = 0; n < 4; n++)                           // A: 128 rows
            cp16(st + (uint32_t)(rA + n * 32) * 128 + col_sw,
                 pa + (size_t)n * 32 * KDIM);
        #pragma unroll
        for (int n = 0; n < 8; n++)                           // B: 256 rows
            cp16(st + A_BYTES + (uint32_t)(rA + n * 32) * 128 + col_sw,
                 pb + (size_t)n * 32 * KDIM);
        asm volatile("cp.async.commit_group;" ::: "memory");
    };

    float acc[4][4][2][4];                                    // [mf][p][h][4] = 128 regs
    #pragma unroll
    for (int mf = 0; mf < 4; mf++)
        #pragma unroll
        for (int p = 0; p < 4; p++)
            #pragma unroll
            for (int h = 0; h < 2; h++)
                acc[mf][p][h][0] = acc[mf][p][h][1] =
                acc[mf][p][h][2] = acc[mf][p][h][3] = 0.f;

    produce(0);
    produce(1);

    for (int v = 0; v < V; v++) {
        asm volatile("cp.async.wait_group 1;" ::: "memory");
        __syncthreads();
        if (v + 2 < V) produce(v + 2);
        else asm volatile("cp.async.commit_group;" ::: "memory");

        const uint32_t st = sb + (uint32_t)(((uint32_t)v) % STAGES) * STAGE_BYTES;
        #pragma unroll
        for (int ks = 0; ks < 4; ks++) {
            const uint32_t colk = ((uint32_t)(ks * 32) + khi) ^ kxor;
            uint32_t a[4][4];
            #pragma unroll
            for (int mf = 0; mf < 4; mf++)
                ldm_x4(a[mf], st + rowA_off + (uint32_t)mf * 2048 + colk);
            uint32_t b[4][4];
            #pragma unroll
            for (int p = 0; p < 4; p++)
                ldm_x4(b[p], st + rowB_off + (uint32_t)p * 2048 + colk);
            #pragma unroll
            for (int mf = 0; mf < 4; mf++) {
                #pragma unroll
                for (int p = 0; p < 4; p++) {
                    hmma(acc[mf][p][0], a[mf], b[p][0], b[p][2]);  // n [p*16+0, +8)
                    hmma(acc[mf][p][1], a[mf], b[p][1], b[p][3]);  // n [p*16+8, +16)
                }
            }
        }

        if ((v & 31) == 31) {
            // epilogue for finished tile
            const int t  = bid + (v >> 5) * GRID;
            const int m0 = (t >> 3) * BM;
            const int n0 = (t & 7) * BN;
            const int rbase = m0 + wm * 64 + (lane >> 2);
            const int cbase = n0 + wn * 64 + (lane & 3) * 2;
            #pragma unroll
            for (int mf = 0; mf < 4; mf++) {
                #pragma unroll
                for (int p = 0; p < 4; p++) {
                    #pragma unroll
                    for (int h = 0; h < 2; h++) {
                        const int col = cbase + p * 16 + h * 8;
                        float* o0 = out + (size_t)(rbase + mf * 16) * NDIM + col;
                        float* o1 = out + (size_t)(rbase + mf * 16 + 8) * NDIM + col;
                        *reinterpret_cast<float2*>(o0) =
                            make_float2(acc[mf][p][h][0], acc[mf][p][h][1]);
                        *reinterpret_cast<float2*>(o1) =
                            make_float2(acc[mf][p][h][2], acc[mf][p][h][3]);
                        acc[mf][p][h][0] = acc[mf][p][h][1] = 0.f;
                        acc[mf][p][h][2] = acc[mf][p][h][3] = 0.f;
                    }
                }
            }
        }
    }
}

// ============================ host launcher ============================
extern "C" void kernel_launch(void* const* d_in, const int* in_sizes, int n_in,
                              void* d_out, int out_size) {
    (void)in_sizes; (void)n_in; (void)out_size;
    const float* x  = (const float*)d_in[0];
    const float* w  = (const float*)d_in[1];
    const float* rv = (const float*)d_in[2];
    float* out = (float*)d_out;

    qx_kernel<<<16384, 256>>>(x);        // 16384*256*8 = 16384*2048
    qw_kernel<<<2048, 256>>>(w, rv);     // 2048*256*8  = 2048*2048

    static bool configured = false;
    if (!configured) {
        cudaFuncSetAttribute((const void*)gemm_kernel,
                             cudaFuncAttributeMaxDynamicSharedMemorySize, SMEM_BYTES);
        configured = true;
    }
    gemm_kernel<<<GRID, 256, SMEM_BYTES>>>(out);
}